// round 1
// baseline (speedup 1.0000x reference)
#include <cuda_runtime.h>
#include <cuda_bf16.h>
#include <math.h>

#define BB 16
#define HH 480
#define WW 640
#define HW (HH*WW)
#define CC 256
#define HCC 60
#define WCC 80
#define KK 400
#define BORDER 4
#define RADIUS 3
#define CAND_CAP 24576

// output layout: kpts (16,400,2) | scores (16,400) | sampled (16,256,400) | heatmap (16,1,480,640)
#define OFF_KPTS 0
#define OFF_SCORES (BB*KK*2)                 // 12800
#define OFF_SAMPLED (OFF_SCORES + BB*KK)     // 19200
#define OFF_HEAT (OFF_SAMPLED + BB*CC*KK)    // 1657600

__device__ float g_rowmax[BB*HW];
__device__ unsigned long long g_cand[BB*CAND_CAP];
__device__ int g_count[BB];
__device__ int g_topidx[BB*KK];

__global__ void k_reset() {
    int i = threadIdx.x;
    if (i < BB) g_count[i] = 0;
}

// row-wise 7-tap max + passthrough copy of heatmap to output
__global__ void k_rowmax_copy(const float* __restrict__ h, float* __restrict__ out) {
    int i = blockIdx.x * blockDim.x + threadIdx.x;
    if (i >= BB*HW) return;
    float v = h[i];
    out[OFF_HEAT + i] = v;
    int x = i % WW;
    const float* row = h + (i - x);
    float m = v;
    int lo = x - RADIUS; if (lo < 0) lo = 0;
    int hi = x + RADIUS; if (hi > WW-1) hi = WW-1;
    #pragma unroll 1
    for (int xx = lo; xx <= hi; ++xx) m = fmaxf(m, row[xx]);
    g_rowmax[i] = m;
}

// column-wise 7-tap max over rowmax => full 7x7 pooled; emit candidates
__global__ void k_candidates(const float* __restrict__ h) {
    int i = blockIdx.x * blockDim.x + threadIdx.x;
    if (i >= BB*HW) return;
    int b = i / HW;
    int r = i - b*HW;
    int y = r / WW;
    int x = r - y*WW;
    if (x < BORDER || x >= WW-BORDER || y < BORDER || y >= HH-BORDER) return;
    float v = h[i];
    if (!(v > 0.f)) return;
    // y in [4,475] => y-3..y+3 fully in range
    const float* rm = g_rowmax + b*HW + x;
    float m = v;
    #pragma unroll
    for (int dy = -RADIUS; dy <= RADIUS; ++dy)
        m = fmaxf(m, rm[(y+dy)*WW]);
    if (v >= m) {
        int slot = atomicAdd(&g_count[b], 1);
        if (slot < CAND_CAP) {
            unsigned int vb = __float_as_uint(v);
            unsigned long long key =
                ((unsigned long long)(0xFFFFFFFFu - vb) << 32) | (unsigned int)r;
            g_cand[b*CAND_CAP + slot] = key;
        }
    }
}

// per-batch exact top-K (sorted desc, ties by index asc) via 64-bit radix-select
// + bitonic sort of the surviving <=512 keys. One block per batch.
__global__ __launch_bounds__(1024)
void k_select(float* __restrict__ out) {
    __shared__ unsigned int bins[256];
    __shared__ unsigned long long s_keys[512];
    __shared__ int s_cnt;
    __shared__ unsigned long long s_prefix;
    __shared__ int s_rank;

    int b = blockIdx.x;
    int tid = threadIdx.x;
    int n = g_count[b];
    if (n > CAND_CAP) n = CAND_CAP;
    const unsigned long long* keys = g_cand + (size_t)b*CAND_CAP;

    if (tid == 0) { s_prefix = 0ULL; s_rank = KK; }
    __syncthreads();

    // 8 MSB-first radix passes -> exact key of the KK-th smallest
    for (int shift = 56; shift >= 0; shift -= 8) {
        if (tid < 256) bins[tid] = 0u;
        __syncthreads();
        unsigned long long maskhi = (shift == 56) ? 0ULL : (~0ULL << (shift + 8));
        unsigned long long pref = s_prefix;
        for (int i = tid; i < n; i += blockDim.x) {
            unsigned long long key = keys[i];
            if ((key & maskhi) == pref)
                atomicAdd(&bins[(unsigned)(key >> shift) & 0xFFu], 1u);
        }
        __syncthreads();
        if (tid == 0) {
            int acc = 0, bsel = 255, rk = s_rank;
            for (int bb2 = 0; bb2 < 256; ++bb2) {
                int c = (int)bins[bb2];
                if (acc + c >= rk) { bsel = bb2; break; }
                acc += c;
            }
            s_prefix = pref | ((unsigned long long)bsel << shift);
            s_rank = rk - acc;
        }
        __syncthreads();
    }
    unsigned long long kth = s_prefix;

    if (tid == 0) s_cnt = 0;
    __syncthreads();
    for (int i = tid; i < n; i += blockDim.x) {
        unsigned long long key = keys[i];
        if (key <= kth) {
            int p = atomicAdd(&s_cnt, 1);
            if (p < 512) s_keys[p] = key;
        }
    }
    __syncthreads();
    int cnt = s_cnt; if (cnt > 512) cnt = 512;
    for (int i = tid; i < 512; i += blockDim.x)
        if (i >= cnt) s_keys[i] = ~0ULL;
    __syncthreads();

    // bitonic sort 512 ascending
    for (unsigned kk2 = 2; kk2 <= 512; kk2 <<= 1) {
        for (unsigned j = kk2 >> 1; j > 0; j >>= 1) {
            for (unsigned i = tid; i < 512; i += blockDim.x) {
                unsigned ixj = i ^ j;
                if (ixj > i) {
                    bool asc = ((i & kk2) == 0);
                    unsigned long long a = s_keys[i], c = s_keys[ixj];
                    if ((a > c) == asc) { s_keys[i] = c; s_keys[ixj] = a; }
                }
            }
            __syncthreads();
        }
    }

    for (int k = tid; k < KK; k += blockDim.x) {
        unsigned long long key = s_keys[k];
        unsigned int vb = 0xFFFFFFFFu - (unsigned int)(key >> 32);
        float val = __uint_as_float(vb);
        int idx = (int)(unsigned int)(key & 0xFFFFFFFFu);
        int y = idx / WW;
        int x = idx - y*WW;
        out[OFF_KPTS + ((size_t)b*KK + k)*2 + 0] = (float)x + 0.5f;
        out[OFF_KPTS + ((size_t)b*KK + k)*2 + 1] = (float)y + 0.5f;
        out[OFF_SCORES + (size_t)b*KK + k] = val;
        g_topidx[b*KK + k] = idx;
    }
}

// bilinear descriptor sampling + L2 normalize over C=256.
// grid (K, B), block 256 (thread = channel)
__global__ __launch_bounds__(256)
void k_sample(const float* __restrict__ desc, float* __restrict__ out) {
    int k = blockIdx.x;
    int b = blockIdx.y;
    int c = threadIdx.x;

    int idx = g_topidx[b*KK + k];
    int iy = idx / WW;
    int ix = idx - iy*WW;
    float kx = (float)ix + 0.5f;
    float ky = (float)iy + 0.5f;

    // gx = ((kx - 3.5)/635.5) * (wc-1), gy analog
    const float SCALEX = 635.5f; // 80*8 - 4 - 0.5
    const float SCALEY = 475.5f; // 60*8 - 4 - 0.5
    float ux = (kx - 3.5f) / SCALEX;
    float uy = (ky - 3.5f) / SCALEY;
    float gx = ((ux * 2.f - 1.f) + 1.f) * 0.5f * (float)(WCC - 1);
    float gy = ((uy * 2.f - 1.f) + 1.f) * 0.5f * (float)(HCC - 1);

    float x0f = floorf(gx), y0f = floorf(gy);
    float wx = gx - x0f, wy = gy - y0f;
    int x0 = (int)x0f; x0 = min(max(x0, 0), WCC - 1);
    int x1 = min(x0 + 1, WCC - 1);
    int y0 = (int)y0f; y0 = min(max(y0, 0), HCC - 1);
    int y1 = min(y0 + 1, HCC - 1);

    const float* d = desc + ((size_t)b*CC + c) * (HCC*WCC);
    float d00 = d[y0*WCC + x0];
    float d01 = d[y0*WCC + x1];
    float d10 = d[y1*WCC + x0];
    float d11 = d[y1*WCC + x1];
    float v = d00*(1.f-wx)*(1.f-wy) + d01*wx*(1.f-wy)
            + d10*(1.f-wx)*wy     + d11*wx*wy;

    // block reduce sum(v*v)
    float s = v*v;
    #pragma unroll
    for (int o = 16; o > 0; o >>= 1) s += __shfl_xor_sync(0xFFFFFFFFu, s, o);
    __shared__ float ws[8];
    __shared__ float inv_norm;
    if ((c & 31) == 0) ws[c >> 5] = s;
    __syncthreads();
    if (c == 0) {
        float t = 0.f;
        #pragma unroll
        for (int i = 0; i < 8; ++i) t += ws[i];
        inv_norm = 1.0f / sqrtf(t + 1e-12f);
    }
    __syncthreads();

    out[OFF_SAMPLED + ((size_t)b*CC + c)*KK + k] = v * inv_norm;
}

extern "C" void kernel_launch(void* const* d_in, const int* in_sizes, int n_in,
                              void* d_out, int out_size) {
    const float* heat = (const float*)d_in[0];
    const float* desc = (const float*)d_in[1];
    float* out = (float*)d_out;

    k_reset<<<1, 32>>>();

    int total = BB*HW;
    int threads = 256;
    int blocks = (total + threads - 1) / threads;
    k_rowmax_copy<<<blocks, threads>>>(heat, out);
    k_candidates<<<blocks, threads>>>(heat);
    k_select<<<BB, 1024>>>(out);

    dim3 sgrid(KK, BB);
    k_sample<<<sgrid, CC>>>(desc, out);
}

// round 3
// speedup vs baseline: 1.3843x; 1.3843x over previous
#include <cuda_runtime.h>
#include <cuda_bf16.h>
#include <math.h>

#define BB 16
#define HH 480
#define WW 640
#define HW (HH*WW)
#define CC 256
#define HCC 60
#define WCC 80
#define KK 400
#define CAND_CAP 24576

#define TX 128
#define TXH 134      // TX + 6 halo
#define TYI 38
#define RYH 44       // TYI + 6 halo
#define NBX (WW / TX)              // 5
#define NBY ((HH + TYI - 1) / TYI) // 13

// output layout: kpts (16,400,2) | scores (16,400) | sampled (16,256,400) | heatmap (16,1,480,640)
#define OFF_KPTS 0
#define OFF_SCORES (BB*KK*2)
#define OFF_SAMPLED (OFF_SCORES + BB*KK)
#define OFF_HEAT (OFF_SAMPLED + BB*CC*KK)

__device__ unsigned int g_cval[BB*CAND_CAP];
__device__ unsigned int g_cidx[BB*CAND_CAP];
__device__ int g_count[BB];
__device__ int g_topidx[BB*KK];

__global__ void k_reset() {
    int i = threadIdx.x;
    if (i < BB) g_count[i] = 0;
}

// Fused: heatmap copy + separable 7x7 max + candidate compaction.
// grid (NBX, NBY, BB), block 256, static smem (~47KB).
__global__ __launch_bounds__(256) void k_nms(const float* __restrict__ h,
                                             float* __restrict__ out) {
    __shared__ float s_h[RYH][TXH];
    __shared__ float s_rm[RYH][TXH];

    int b   = blockIdx.z;
    int tx0 = blockIdx.x * TX;
    int ty0 = blockIdx.y * TYI;
    const float* hb = h + (size_t)b*HW;
    float* ob = out + OFF_HEAT + (size_t)b*HW;
    int lane = threadIdx.x & 31;

    // load tile (+halo); fold in the heatmap passthrough for inner pixels
    for (int i = threadIdx.x; i < RYH*TXH; i += 256) {
        int r = i / TXH, cx = i - r*TXH;
        int gy = ty0 - 3 + r, gx = tx0 - 3 + cx;
        float v = 0.f;
        if (gy >= 0 && gy < HH && gx >= 0 && gx < WW) v = hb[gy*WW + gx];
        s_h[r][cx] = v;
        if (r >= 3 && r < 3 + TYI && cx >= 3 && cx < 3 + TX && gy < HH)
            ob[gy*WW + gx] = v;
    }
    __syncthreads();

    // row-wise 7-tap max for the inner columns
    for (int i = threadIdx.x; i < RYH*TX; i += 256) {
        int r = i / TX, c = i - r*TX;
        int cx = c + 3;
        float m = s_h[r][cx-3];
        #pragma unroll
        for (int j = -2; j <= 3; ++j) m = fmaxf(m, s_h[r][cx+j]);
        s_rm[r][cx] = m;
    }
    __syncthreads();

    // column-wise 7-tap max + warp-aggregated candidate append.
    // TYI*TX = 4864 = 19*256 exactly -> uniform trip count for all lanes.
    #pragma unroll 1
    for (int i = threadIdx.x; i < TYI*TX; i += 256) {
        int r = i / TX, c = i - r*TX;
        int rr = r + 3, cx = c + 3;
        int gy = ty0 + r, gx = tx0 + c;
        float v = s_h[rr][cx];
        bool pred = false;
        if (gy >= 4 && gy < HH-4 && gx >= 4 && gx < WW-4) {
            float m = s_rm[rr-3][cx];
            #pragma unroll
            for (int j = -2; j <= 3; ++j) m = fmaxf(m, s_rm[rr+j][cx]);
            pred = (v >= m) && (v > 0.f);
        }
        unsigned mask = __ballot_sync(0xFFFFFFFFu, pred);
        if (pred) {
            int leader = __ffs(mask) - 1;
            int base;
            if (lane == leader) base = atomicAdd(&g_count[b], __popc(mask));
            base = __shfl_sync(mask, base, leader);
            int slot = base + __popc(mask & ((1u << lane) - 1u));
            if (slot < CAND_CAP) {
                g_cval[b*CAND_CAP + slot] = 0xFFFFFFFFu - __float_as_uint(v);
                g_cidx[b*CAND_CAP + slot] = (unsigned)(gy*WW + gx);
            }
        }
    }
}

// exact per-batch top-K: 3-pass wide radix-select on 32-bit complemented value,
// then gather <=512 survivors and bitonic sort by (value,idx). One block/batch.
__global__ __launch_bounds__(1024) void k_select(float* __restrict__ out) {
    __shared__ unsigned int bins[2048];
    __shared__ int s_warp[32];
    __shared__ unsigned int s_bin;
    __shared__ int s_newrank;
    __shared__ unsigned long long s_keys[512];
    __shared__ int s_cnt;

    int b = blockIdx.x;
    int tid = threadIdx.x;
    int lane = tid & 31, wid = tid >> 5;
    int n = g_count[b]; if (n > CAND_CAP) n = CAND_CAP;
    const unsigned int* vals = g_cval + (size_t)b*CAND_CAP;
    const unsigned int* idxs = g_cidx + (size_t)b*CAND_CAP;

    int nIter = (n + 1023) >> 10;
    unsigned int pivot = 0xFFFFFFFFu;
    int rank = KK;

    if (n >= KK) {
        unsigned int prefix = 0;
        #pragma unroll
        for (int p = 0; p < 3; ++p) {
            int shift    = (p == 0) ? 21 : (p == 1) ? 10 : 0;
            int nbins    = (p == 2) ? 1024 : 2048;
            int topshift = shift + ((p == 2) ? 10 : 11);

            for (int i = tid; i < nbins; i += 1024) bins[i] = 0;
            __syncthreads();

            for (int it = 0; it < nIter; ++it) {      // uniform trip count
                int i = (it << 10) + tid;
                bool active = (i < n);
                unsigned int vk = active ? vals[i] : 0u;
                bool ok = active && ((p == 0) || ((vk >> topshift) == prefix));
                unsigned int bin = (vk >> shift) & (unsigned)(nbins - 1);
                unsigned int m = __ballot_sync(0xFFFFFFFFu, ok);
                if (ok) {
                    unsigned int peers = __match_any_sync(m, bin);
                    int ldr = __ffs(peers) - 1;
                    if (lane == ldr) atomicAdd(&bins[bin], (unsigned)__popc(peers));
                }
            }
            __syncthreads();

            // parallel scan over bins: thread owns bins[2t], bins[2t+1]
            int c0 = 0, c1 = 0;
            if (2*tid < nbins) { c0 = (int)bins[2*tid]; c1 = (int)bins[2*tid + 1]; }
            int s = c0 + c1;
            int v2 = s;
            #pragma unroll
            for (int o = 1; o < 32; o <<= 1) {
                int t = __shfl_up_sync(0xFFFFFFFFu, v2, o);
                if (lane >= o) v2 += t;
            }
            if (lane == 31) s_warp[wid] = v2;
            __syncthreads();
            if (wid == 0) {
                int ws = s_warp[lane];
                #pragma unroll
                for (int o = 1; o < 32; o <<= 1) {
                    int t = __shfl_up_sync(0xFFFFFFFFu, ws, o);
                    if (lane >= o) ws += t;
                }
                s_warp[lane] = ws;
            }
            __syncthreads();
            int incl = v2 + (wid > 0 ? s_warp[wid - 1] : 0);
            int excl = incl - s;
            if (rank > excl && rank <= excl + c0) {
                s_bin = (unsigned)(2*tid); s_newrank = rank - excl;
            } else if (rank > excl + c0 && rank <= incl) {
                s_bin = (unsigned)(2*tid + 1); s_newrank = rank - excl - c0;
            }
            __syncthreads();
            prefix = (p == 0) ? s_bin : ((prefix << ((p == 2) ? 10 : 11)) | s_bin);
            rank = s_newrank;
            __syncthreads();
        }
        pivot = prefix;
    }

    // gather: strictly-less first (count < KK guaranteed), then equals
    if (tid == 0) s_cnt = 0;
    __syncthreads();
    #pragma unroll
    for (int phase = 0; phase < 2; ++phase) {
        for (int it = 0; it < nIter; ++it) {          // uniform trip count
            int i = (it << 10) + tid;
            bool active = (i < n);
            unsigned int vk = active ? vals[i] : 0u;
            bool take = active && ((phase == 0) ? (vk < pivot) : (vk == pivot));
            unsigned int m = __ballot_sync(0xFFFFFFFFu, take);
            if (take) {
                int ldr = __ffs(m) - 1;
                int base;
                if (lane == ldr) base = atomicAdd(&s_cnt, __popc(m));
                base = __shfl_sync(m, base, ldr);
                int slot = base + __popc(m & ((1u << lane) - 1u));
                if (slot < 512)
                    s_keys[slot] = ((unsigned long long)vk << 32) | idxs[i];
            }
        }
        __syncthreads();
    }
    int cnt = s_cnt; if (cnt > 512) cnt = 512;
    for (int i = tid; i < 512; i += 1024)
        if (i >= cnt) s_keys[i] = ~0ULL;
    __syncthreads();

    // bitonic sort 512 ascending
    for (unsigned kk2 = 2; kk2 <= 512; kk2 <<= 1) {
        for (unsigned j = kk2 >> 1; j > 0; j >>= 1) {
            for (unsigned i = tid; i < 512; i += 1024) {
                unsigned ixj = i ^ j;
                if (ixj > i) {
                    bool asc = ((i & kk2) == 0);
                    unsigned long long a = s_keys[i], c = s_keys[ixj];
                    if ((a > c) == asc) { s_keys[i] = c; s_keys[ixj] = a; }
                }
            }
            __syncthreads();
        }
    }

    for (int k = tid; k < KK; k += 1024) {
        unsigned long long key = s_keys[k];
        unsigned int vb = 0xFFFFFFFFu - (unsigned int)(key >> 32);
        int idx = (int)(unsigned int)(key & 0xFFFFFFFFu);
        int y = idx / WW;
        int x = idx - y*WW;
        out[OFF_KPTS + ((size_t)b*KK + k)*2 + 0] = (float)x + 0.5f;
        out[OFF_KPTS + ((size_t)b*KK + k)*2 + 1] = (float)y + 0.5f;
        out[OFF_SCORES + (size_t)b*KK + k] = __uint_as_float(vb);
        g_topidx[b*KK + k] = idx;
    }
}

// bilinear descriptor sample + L2 norm. grid (KK/8, BB), block 256 (thread = channel).
// 8 keypoints per block -> per-thread contiguous 32B output run (2x float4 store).
__global__ __launch_bounds__(256) void k_sample(const float* __restrict__ desc,
                                                float* __restrict__ out) {
    __shared__ int   s_off[8][4];
    __shared__ float s_wq[8][4];
    __shared__ float s_norm[8];
    __shared__ float s_inv[8];

    int b  = blockIdx.y;
    int k0 = blockIdx.x * 8;
    int c  = threadIdx.x;
    int lane = c & 31;

    if (c < 8) {
        int idx = g_topidx[b*KK + k0 + c];
        int iy = idx / WW;
        int ix = idx - iy*WW;
        float kx = (float)ix + 0.5f;
        float ky = (float)iy + 0.5f;
        float ux = (kx - 3.5f) / 635.5f;   // wc*S - S/2 - 0.5
        float uy = (ky - 3.5f) / 475.5f;   // hc*S - S/2 - 0.5
        float gx = ((ux * 2.f - 1.f) + 1.f) * 0.5f * (float)(WCC - 1);
        float gy = ((uy * 2.f - 1.f) + 1.f) * 0.5f * (float)(HCC - 1);
        float x0f = floorf(gx), y0f = floorf(gy);
        float wx = gx - x0f, wy = gy - y0f;
        int x0 = (int)x0f; x0 = min(max(x0, 0), WCC - 1);
        int x1 = min(x0 + 1, WCC - 1);
        int y0 = (int)y0f; y0 = min(max(y0, 0), HCC - 1);
        int y1 = min(y0 + 1, HCC - 1);
        s_off[c][0] = y0*WCC + x0;
        s_off[c][1] = y0*WCC + x1;
        s_off[c][2] = y1*WCC + x0;
        s_off[c][3] = y1*WCC + x1;
        s_wq[c][0] = (1.f - wx) * (1.f - wy);
        s_wq[c][1] = wx * (1.f - wy);
        s_wq[c][2] = (1.f - wx) * wy;
        s_wq[c][3] = wx * wy;
        s_norm[c] = 0.f;
    }
    __syncthreads();

    const float* dptr = desc + ((size_t)b*CC + c) * (HCC*WCC);
    float vv[8];
    #pragma unroll
    for (int kk = 0; kk < 8; ++kk) {
        float d00 = __ldg(dptr + s_off[kk][0]);
        float d01 = __ldg(dptr + s_off[kk][1]);
        float d10 = __ldg(dptr + s_off[kk][2]);
        float d11 = __ldg(dptr + s_off[kk][3]);
        float v = d00*s_wq[kk][0] + d01*s_wq[kk][1]
                + d10*s_wq[kk][2] + d11*s_wq[kk][3];
        vv[kk] = v;
        float s = v * v;
        #pragma unroll
        for (int o = 16; o > 0; o >>= 1) s += __shfl_xor_sync(0xFFFFFFFFu, s, o);
        if (lane == 0) atomicAdd(&s_norm[kk], s);
    }
    __syncthreads();
    if (c < 8) s_inv[c] = 1.0f / sqrtf(s_norm[c] + 1e-12f);
    __syncthreads();

    float4 o0, o1;
    o0.x = vv[0]*s_inv[0]; o0.y = vv[1]*s_inv[1];
    o0.z = vv[2]*s_inv[2]; o0.w = vv[3]*s_inv[3];
    o1.x = vv[4]*s_inv[4]; o1.y = vv[5]*s_inv[5];
    o1.z = vv[6]*s_inv[6]; o1.w = vv[7]*s_inv[7];
    float4* op = reinterpret_cast<float4*>(out + OFF_SAMPLED + ((size_t)b*CC + c)*KK + k0);
    op[0] = o0;
    op[1] = o1;
}

extern "C" void kernel_launch(void* const* d_in, const int* in_sizes, int n_in,
                              void* d_out, int out_size) {
    const float* heat = (const float*)d_in[0];
    const float* desc = (const float*)d_in[1];
    float* out = (float*)d_out;

    k_reset<<<1, 32>>>();

    dim3 ngrid(NBX, NBY, BB);
    k_nms<<<ngrid, 256>>>(heat, out);

    k_select<<<BB, 1024>>>(out);

    dim3 sgrid(KK / 8, BB);
    k_sample<<<sgrid, 256>>>(desc, out);
}

// round 4
// speedup vs baseline: 1.4621x; 1.0562x over previous
#include <cuda_runtime.h>
#include <cuda_bf16.h>
#include <math.h>

#define BB 16
#define HH 480
#define WW 640
#define HW (HH*WW)
#define CC 256
#define HCC 60
#define WCC 80
#define KK 400
#define CAND_CAP 24576

#define TX 128
#define TXH 134      // TX + 6 halo
#define TYI 38
#define RYH 44       // TYI + 6 halo
#define NBX (WW / TX)              // 5
#define NBY ((HH + TYI - 1) / TYI) // 13

// output layout: kpts (16,400,2) | scores (16,400) | sampled (16,256,400) | heatmap (16,1,480,640)
#define OFF_KPTS 0
#define OFF_SCORES (BB*KK*2)
#define OFF_SAMPLED (OFF_SCORES + BB*KK)
#define OFF_HEAT (OFF_SAMPLED + BB*CC*KK)

__device__ unsigned int g_cval[BB*CAND_CAP];
__device__ unsigned int g_cidx[BB*CAND_CAP];
__device__ int g_count[BB];      // zero-initialized at load; re-zeroed by k_select tail
__device__ int g_topidx[BB*KK];

// Fused: heatmap copy + separable 7x7 max + candidate compaction.
// grid (NBX, NBY, BB), block 256, static smem (~47KB).
__global__ __launch_bounds__(256) void k_nms(const float* __restrict__ h,
                                             float* __restrict__ out) {
    __shared__ float s_h[RYH][TXH];
    __shared__ float s_rm[RYH][TXH];

    int b   = blockIdx.z;
    int tx0 = blockIdx.x * TX;
    int ty0 = blockIdx.y * TYI;
    const float* hb = h + (size_t)b*HW;
    float* ob = out + OFF_HEAT + (size_t)b*HW;
    int lane = threadIdx.x & 31;

    // load tile (+halo); fold in the heatmap passthrough for inner pixels
    for (int i = threadIdx.x; i < RYH*TXH; i += 256) {
        int r = i / TXH, cx = i - r*TXH;
        int gy = ty0 - 3 + r, gx = tx0 - 3 + cx;
        float v = 0.f;
        if (gy >= 0 && gy < HH && gx >= 0 && gx < WW) v = hb[gy*WW + gx];
        s_h[r][cx] = v;
        if (r >= 3 && r < 3 + TYI && cx >= 3 && cx < 3 + TX && gy < HH)
            ob[gy*WW + gx] = v;
    }
    __syncthreads();

    // row-wise 7-tap max for the inner columns
    for (int i = threadIdx.x; i < RYH*TX; i += 256) {
        int r = i / TX, c = i - r*TX;
        int cx = c + 3;
        float m = s_h[r][cx-3];
        #pragma unroll
        for (int j = -2; j <= 3; ++j) m = fmaxf(m, s_h[r][cx+j]);
        s_rm[r][cx] = m;
    }
    __syncthreads();

    // column-wise 7-tap max + warp-aggregated candidate append.
    // TYI*TX = 4864 = 19*256 exactly -> uniform trip count for all lanes.
    #pragma unroll 1
    for (int i = threadIdx.x; i < TYI*TX; i += 256) {
        int r = i / TX, c = i - r*TX;
        int rr = r + 3, cx = c + 3;
        int gy = ty0 + r, gx = tx0 + c;
        float v = s_h[rr][cx];
        bool pred = false;
        if (gy >= 4 && gy < HH-4 && gx >= 4 && gx < WW-4) {
            float m = s_rm[rr-3][cx];
            #pragma unroll
            for (int j = -2; j <= 3; ++j) m = fmaxf(m, s_rm[rr+j][cx]);
            pred = (v >= m) && (v > 0.f);
        }
        unsigned mask = __ballot_sync(0xFFFFFFFFu, pred);
        if (pred) {
            int leader = __ffs(mask) - 1;
            int base;
            if (lane == leader) base = atomicAdd(&g_count[b], __popc(mask));
            base = __shfl_sync(mask, base, leader);
            int slot = base + __popc(mask & ((1u << lane) - 1u));
            if (slot < CAND_CAP) {
                g_cval[b*CAND_CAP + slot] = 0xFFFFFFFFu - __float_as_uint(v);
                g_cidx[b*CAND_CAP + slot] = (unsigned)(gy*WW + gx);
            }
        }
    }
}

// exact per-batch top-K: 3-pass wide radix-select on 32-bit complemented value,
// then gather <=512 survivors and bitonic sort by (value,idx). One block/batch.
// Tail also resets g_count[b] for the next graph replay.
__global__ __launch_bounds__(1024) void k_select(float* __restrict__ out) {
    __shared__ unsigned int bins[2048];
    __shared__ int s_warp[32];
    __shared__ unsigned int s_bin;
    __shared__ int s_newrank;
    __shared__ unsigned long long s_keys[512];
    __shared__ int s_cnt;

    int b = blockIdx.x;
    int tid = threadIdx.x;
    int lane = tid & 31, wid = tid >> 5;
    int n = g_count[b]; if (n > CAND_CAP) n = CAND_CAP;
    const unsigned int* vals = g_cval + (size_t)b*CAND_CAP;
    const unsigned int* idxs = g_cidx + (size_t)b*CAND_CAP;

    int nIter = (n + 1023) >> 10;
    unsigned int pivot = 0xFFFFFFFFu;
    int rank = KK;

    if (n >= KK) {
        unsigned int prefix = 0;
        #pragma unroll
        for (int p = 0; p < 3; ++p) {
            int shift    = (p == 0) ? 21 : (p == 1) ? 10 : 0;
            int nbins    = (p == 2) ? 1024 : 2048;
            int topshift = shift + ((p == 2) ? 10 : 11);

            for (int i = tid; i < nbins; i += 1024) bins[i] = 0;
            __syncthreads();

            for (int it = 0; it < nIter; ++it) {      // uniform trip count
                int i = (it << 10) + tid;
                bool active = (i < n);
                unsigned int vk = active ? vals[i] : 0u;
                bool ok = active && ((p == 0) || ((vk >> topshift) == prefix));
                unsigned int bin = (vk >> shift) & (unsigned)(nbins - 1);
                unsigned int m = __ballot_sync(0xFFFFFFFFu, ok);
                if (ok) {
                    unsigned int peers = __match_any_sync(m, bin);
                    int ldr = __ffs(peers) - 1;
                    if (lane == ldr) atomicAdd(&bins[bin], (unsigned)__popc(peers));
                }
            }
            __syncthreads();

            // parallel scan over bins: thread owns bins[2t], bins[2t+1]
            int c0 = 0, c1 = 0;
            if (2*tid < nbins) { c0 = (int)bins[2*tid]; c1 = (int)bins[2*tid + 1]; }
            int s = c0 + c1;
            int v2 = s;
            #pragma unroll
            for (int o = 1; o < 32; o <<= 1) {
                int t = __shfl_up_sync(0xFFFFFFFFu, v2, o);
                if (lane >= o) v2 += t;
            }
            if (lane == 31) s_warp[wid] = v2;
            __syncthreads();
            if (wid == 0) {
                int ws = s_warp[lane];
                #pragma unroll
                for (int o = 1; o < 32; o <<= 1) {
                    int t = __shfl_up_sync(0xFFFFFFFFu, ws, o);
                    if (lane >= o) ws += t;
                }
                s_warp[lane] = ws;
            }
            __syncthreads();
            int incl = v2 + (wid > 0 ? s_warp[wid - 1] : 0);
            int excl = incl - s;
            if (rank > excl && rank <= excl + c0) {
                s_bin = (unsigned)(2*tid); s_newrank = rank - excl;
            } else if (rank > excl + c0 && rank <= incl) {
                s_bin = (unsigned)(2*tid + 1); s_newrank = rank - excl - c0;
            }
            __syncthreads();
            prefix = (p == 0) ? s_bin : ((prefix << ((p == 2) ? 10 : 11)) | s_bin);
            rank = s_newrank;
            __syncthreads();
        }
        pivot = prefix;
    }

    // gather: strictly-less first (count < KK guaranteed), then equals
    if (tid == 0) s_cnt = 0;
    __syncthreads();
    #pragma unroll
    for (int phase = 0; phase < 2; ++phase) {
        for (int it = 0; it < nIter; ++it) {          // uniform trip count
            int i = (it << 10) + tid;
            bool active = (i < n);
            unsigned int vk = active ? vals[i] : 0u;
            bool take = active && ((phase == 0) ? (vk < pivot) : (vk == pivot));
            unsigned int m = __ballot_sync(0xFFFFFFFFu, take);
            if (take) {
                int ldr = __ffs(m) - 1;
                int base;
                if (lane == ldr) base = atomicAdd(&s_cnt, __popc(m));
                base = __shfl_sync(m, base, ldr);
                int slot = base + __popc(m & ((1u << lane) - 1u));
                if (slot < 512)
                    s_keys[slot] = ((unsigned long long)vk << 32) | idxs[i];
            }
        }
        __syncthreads();
    }
    int cnt = s_cnt; if (cnt > 512) cnt = 512;
    for (int i = tid; i < 512; i += 1024)
        if (i >= cnt) s_keys[i] = ~0ULL;
    __syncthreads();

    // bitonic sort 512 ascending
    for (unsigned kk2 = 2; kk2 <= 512; kk2 <<= 1) {
        for (unsigned j = kk2 >> 1; j > 0; j >>= 1) {
            for (unsigned i = tid; i < 512; i += 1024) {
                unsigned ixj = i ^ j;
                if (ixj > i) {
                    bool asc = ((i & kk2) == 0);
                    unsigned long long a = s_keys[i], c = s_keys[ixj];
                    if ((a > c) == asc) { s_keys[i] = c; s_keys[ixj] = a; }
                }
            }
            __syncthreads();
        }
    }

    for (int k = tid; k < KK; k += 1024) {
        unsigned long long key = s_keys[k];
        unsigned int vb = 0xFFFFFFFFu - (unsigned int)(key >> 32);
        int idx = (int)(unsigned int)(key & 0xFFFFFFFFu);
        int y = idx / WW;
        int x = idx - y*WW;
        out[OFF_KPTS + ((size_t)b*KK + k)*2 + 0] = (float)x + 0.5f;
        out[OFF_KPTS + ((size_t)b*KK + k)*2 + 1] = (float)y + 0.5f;
        out[OFF_SCORES + (size_t)b*KK + k] = __uint_as_float(vb);
        g_topidx[b*KK + k] = idx;
    }

    // reset for the next replay (this block's batch only)
    if (tid == 0) g_count[b] = 0;
}

// bilinear descriptor sample + L2 norm. grid (KK/8, BB), block 256 (thread = channel).
// float4 corner gather: x1 = x0+1 always (never clamped), and (y*80+x0)&3 == x0&3
// is uniform per keypoint -> one aligned float4 per row covers both corners
// (75% of kpts); x0&3==3 needs one extra scalar per row (uniform branch).
__global__ __launch_bounds__(256) void k_sample(const float* __restrict__ desc,
                                                float* __restrict__ out) {
    __shared__ int   s_a0[8];    // float4 index of row y0
    __shared__ int   s_a1[8];    // float4 index of row y1
    __shared__ int   s_sh[8];    // x0 & 3
    __shared__ float s_wq[8][4];
    __shared__ float s_norm[8];
    __shared__ float s_inv[8];

    int b  = blockIdx.y;
    int k0 = blockIdx.x * 8;
    int c  = threadIdx.x;
    int lane = c & 31;

    if (c < 8) {
        int idx = g_topidx[b*KK + k0 + c];
        int iy = idx / WW;
        int ix = idx - iy*WW;
        float kx = (float)ix + 0.5f;
        float ky = (float)iy + 0.5f;
        float ux = (kx - 3.5f) / 635.5f;   // wc*S - S/2 - 0.5
        float uy = (ky - 3.5f) / 475.5f;   // hc*S - S/2 - 0.5
        float gx = ((ux * 2.f - 1.f) + 1.f) * 0.5f * (float)(WCC - 1);
        float gy = ((uy * 2.f - 1.f) + 1.f) * 0.5f * (float)(HCC - 1);
        float x0f = floorf(gx), y0f = floorf(gy);
        float wx = gx - x0f, wy = gy - y0f;
        int x0 = (int)x0f;                 // in [0,78] for this geometry
        int y0 = (int)y0f;                 // in [0,58]
        int off0 = y0*WCC + x0;
        int off1 = (y0+1)*WCC + x0;
        s_sh[c] = x0 & 3;
        s_a0[c] = off0 >> 2;
        s_a1[c] = off1 >> 2;
        s_wq[c][0] = (1.f - wx) * (1.f - wy);
        s_wq[c][1] = wx * (1.f - wy);
        s_wq[c][2] = (1.f - wx) * wy;
        s_wq[c][3] = wx * wy;
        s_norm[c] = 0.f;
    }
    __syncthreads();

    const float*  dp = desc + ((size_t)b*CC + c) * (HCC*WCC);
    const float4* d4 = reinterpret_cast<const float4*>(dp);

    float vv[8];
    #pragma unroll
    for (int kk = 0; kk < 8; ++kk) {
        int a0 = s_a0[kk], a1 = s_a1[kk], sh = s_sh[kk];
        float4 q0 = __ldg(d4 + a0);
        float4 q1 = __ldg(d4 + a1);
        float e00, e01, e10, e11;
        if (sh == 0)      { e00 = q0.x; e01 = q0.y; e10 = q1.x; e11 = q1.y; }
        else if (sh == 1) { e00 = q0.y; e01 = q0.z; e10 = q1.y; e11 = q1.z; }
        else if (sh == 2) { e00 = q0.z; e01 = q0.w; e10 = q1.z; e11 = q1.w; }
        else {
            e00 = q0.w; e10 = q1.w;
            e01 = __ldg(dp + a0*4 + 4);
            e11 = __ldg(dp + a1*4 + 4);
        }
        float v = e00*s_wq[kk][0] + e01*s_wq[kk][1]
                + e10*s_wq[kk][2] + e11*s_wq[kk][3];
        vv[kk] = v;
        float s = v * v;
        #pragma unroll
        for (int o = 16; o > 0; o >>= 1) s += __shfl_xor_sync(0xFFFFFFFFu, s, o);
        if (lane == 0) atomicAdd(&s_norm[kk], s);
    }
    __syncthreads();
    if (c < 8) s_inv[c] = 1.0f / sqrtf(s_norm[c] + 1e-12f);
    __syncthreads();

    float4 o0, o1;
    o0.x = vv[0]*s_inv[0]; o0.y = vv[1]*s_inv[1];
    o0.z = vv[2]*s_inv[2]; o0.w = vv[3]*s_inv[3];
    o1.x = vv[4]*s_inv[4]; o1.y = vv[5]*s_inv[5];
    o1.z = vv[6]*s_inv[6]; o1.w = vv[7]*s_inv[7];
    float4* op = reinterpret_cast<float4*>(out + OFF_SAMPLED + ((size_t)b*CC + c)*KK + k0);
    op[0] = o0;
    op[1] = o1;
}

extern "C" void kernel_launch(void* const* d_in, const int* in_sizes, int n_in,
                              void* d_out, int out_size) {
    const float* heat = (const float*)d_in[0];
    const float* desc = (const float*)d_in[1];
    float* out = (float*)d_out;

    dim3 ngrid(NBX, NBY, BB);
    k_nms<<<ngrid, 256>>>(heat, out);

    k_select<<<BB, 1024>>>(out);

    dim3 sgrid(KK / 8, BB);
    k_sample<<<sgrid, 256>>>(desc, out);
}